// round 5
// baseline (speedup 1.0000x reference)
#include <cuda_runtime.h>
#include <cuda_fp16.h>
#include <cstdint>

#define Ld    2
#define Hd    2048
#define OUTD  1024
#define Bd    64
#define Td    256
#define Kd    4096
#define NCTA  128
#define NTHR  256
#define KC    128

#define WPAD  136
#define APAD  72
#define GPAD  68

#define SMEM_W_BYTES (2 * 64 * WPAD * 2)
#define SMEM_A_BYTES (2 * KC * APAD * 2)
#define SMEM_G_BYTES (64 * GPAD * 4)
#define SMEM_BYTES   (SMEM_W_BYTES + SMEM_A_BYTES + SMEM_G_BYTES)

// ----------------------------- device globals ------------------------------
__device__ __align__(16) __half g_W[Ld][NCTA][64][Kd];     // 128 MB packed gates
__device__ __align__(16) __half g_WoutH[OUTD][Hd];         // 4 MB
__device__ float  g_bias[Ld][NCTA][64];
__device__ float  g_bout[OUTD];
__device__ __align__(16) __half g_H0[2][Hd][Bd];           // layer-0 h ping-pong [k][b]
__device__ __align__(16) __half g_H1all[Td][Hd][Bd];       // layer-1 h, all steps (64 MB)
__device__ __align__(16) __half g_H1init[Hd][Bd];
__device__ __align__(16) __half g_Xzero[Hd][Bd];
__device__ unsigned g_count;

// ------------------------------ PTX helpers --------------------------------
__device__ __forceinline__ unsigned sptr(const void* p) {
    return (unsigned)__cvta_generic_to_shared(p);
}
__device__ __forceinline__ void ldsm4(unsigned& r0, unsigned& r1, unsigned& r2,
                                      unsigned& r3, unsigned a) {
    asm volatile("ldmatrix.sync.aligned.m8n8.x4.shared.b16 {%0,%1,%2,%3},[%4];\n"
                 : "=r"(r0), "=r"(r1), "=r"(r2), "=r"(r3) : "r"(a));
}
__device__ __forceinline__ void ldsm4t(unsigned& r0, unsigned& r1, unsigned& r2,
                                       unsigned& r3, unsigned a) {
    asm volatile("ldmatrix.sync.aligned.m8n8.x4.trans.shared.b16 {%0,%1,%2,%3},[%4];\n"
                 : "=r"(r0), "=r"(r1), "=r"(r2), "=r"(r3) : "r"(a));
}
__device__ __forceinline__ void mma16816(float* d, unsigned a0, unsigned a1,
                                         unsigned a2, unsigned a3,
                                         unsigned b0, unsigned b1) {
    asm volatile(
        "mma.sync.aligned.m16n8k16.row.col.f32.f16.f16.f32 "
        "{%0,%1,%2,%3},{%4,%5,%6,%7},{%8,%9},{%0,%1,%2,%3};\n"
        : "+f"(d[0]), "+f"(d[1]), "+f"(d[2]), "+f"(d[3])
        : "r"(a0), "r"(a1), "r"(a2), "r"(a3), "r"(b0), "r"(b1));
}
__device__ __forceinline__ float sgm(float x) { return 1.f / (1.f + __expf(-x)); }

// Grid barrier: monotonic counter (reset by prep kernel each launch).
// All 128 CTAs are co-resident in wave 1 (grid <= SM count) -> deadlock-free.
__device__ __forceinline__ void gridbar(unsigned& target) {
    __syncthreads();
    if (threadIdx.x == 0) {
        __threadfence();
        target += (unsigned)gridDim.x;
        atomicAdd(&g_count, 1u);
        unsigned v;
        for (;;) {
            asm volatile("ld.acquire.gpu.global.u32 %0, [%1];" : "=r"(v) : "l"(&g_count));
            if (v >= target) break;
            __nanosleep(32);
        }
    }
    __syncthreads();
}

// ------------------------------ prep kernels -------------------------------
__global__ void pack_w_kernel(const float* __restrict__ Wih,
                              const float* __restrict__ Whh) {
    size_t idx = (size_t)blockIdx.x * blockDim.x + threadIdx.x;  // 16,777,216
    int kv = (int)(idx & 1023);
    size_t rest = idx >> 10;
    int r  = (int)(rest & 63);  rest >>= 6;
    int ct = (int)(rest & 127); rest >>= 7;
    int l  = (int)rest;
    if (l >= Ld) return;
    int row = (r >> 4) * 2048 + ct * 16 + (r & 15);   // global gate row (i,f,g,o)
    int k0 = kv * 4;
    const float* src = (k0 < 2048)
        ? (Wih + ((size_t)(l * 8192 + row)) * 2048 + k0)
        : (Whh + ((size_t)(l * 8192 + row)) * 2048 + (k0 - 2048));
    float4 v = *reinterpret_cast<const float4*>(src);
    __half2* dst = reinterpret_cast<__half2*>(&g_W[l][ct][r][k0]);
    dst[0] = __floats2half2_rn(v.x, v.y);
    dst[1] = __floats2half2_rn(v.z, v.w);
}

__global__ void pack_wout_kernel(const float* __restrict__ Wout) {
    int idx = blockIdx.x * blockDim.x + threadIdx.x;  // 524,288
    int k0 = (idx & 511) * 4;
    int row = idx >> 9;
    if (row >= OUTD) return;
    float4 v = *reinterpret_cast<const float4*>(Wout + (size_t)row * Hd + k0);
    __half2* dst = reinterpret_cast<__half2*>(&g_WoutH[row][k0]);
    dst[0] = __floats2half2_rn(v.x, v.y);
    dst[1] = __floats2half2_rn(v.z, v.w);
}

__global__ void pack_misc_kernel(const float* __restrict__ h0,
                                 const float* __restrict__ bih,
                                 const float* __restrict__ bhh,
                                 const float* __restrict__ bout) {
    int i = blockIdx.x * blockDim.x + threadIdx.x;  // 131072
    if (i == 0) g_count = 0u;
    if (i < OUTD) g_bout[i] = bout[i];
    if (i < Ld * NCTA * 64) {
        int r = i & 63, ct = (i >> 6) & 127, l = i >> 13;
        int row = (r >> 4) * 2048 + ct * 16 + (r & 15);
        g_bias[l][ct][r] = bih[l * 8192 + row] + bhh[l * 8192 + row];
    }
    if (i < Hd * Bd) {
        int b = i & 63, j = i >> 6;
        g_H0[1][j][b]  = __float2half_rn(h0[(size_t)b * Hd + j]);          // layer 0
        g_H1init[j][b] = __float2half_rn(h0[(size_t)(Bd + b) * Hd + j]);   // layer 1
        g_Xzero[j][b]  = __float2half_rn(0.f);
    }
}

// --------------------------- 64x64 tile GEMM -------------------------------
// D[64][64] = Wg[64][KTOT] x act[KTOT][64]; act = Xg for k<2048, Hg for k>=2048.
// Result + bias staged into sG [64 rows][GPAD].
template <int KTOT>
__device__ __forceinline__ void gemm64(const __half* __restrict__ Wg,
                                       const __half* __restrict__ Xg,
                                       const __half* __restrict__ Hg,
                                       __half* sW, __half* sA, float* sG,
                                       const float* __restrict__ bias,
                                       int tid, int lane, int wid) {
    constexpr int NCHUNK = KTOT / KC;
    float acc[4][4];
#pragma unroll
    for (int i = 0; i < 4; i++)
#pragma unroll
        for (int j = 0; j < 4; j++) acc[i][j] = 0.f;
    const int wm = wid >> 1, wn = wid & 1;

    uint4 wr[4], ar[4];
#pragma unroll
    for (int i = 0; i < 4; i++) {
        int s = tid + i * NTHR;
        wr[i] = *reinterpret_cast<const uint4*>(Wg + (size_t)(s >> 4) * KTOT + (s & 15) * 8);
    }
#pragma unroll
    for (int i = 0; i < 4; i++) {
        int s = tid + i * NTHR;
        ar[i] = *reinterpret_cast<const uint4*>(Xg + (size_t)(s >> 3) * Bd + (s & 7) * 8);
    }

#pragma unroll 1
    for (int kc = 0; kc < NCHUNK; kc++) {
        __half* sWc = sW + (kc & 1) * 64 * WPAD;
        __half* sAc = sA + (kc & 1) * KC * APAD;
#pragma unroll
        for (int i = 0; i < 4; i++) {
            int s = tid + i * NTHR;
            *reinterpret_cast<uint4*>(sWc + (s >> 4) * WPAD + (s & 15) * 8) = wr[i];
        }
#pragma unroll
        for (int i = 0; i < 4; i++) {
            int s = tid + i * NTHR;
            *reinterpret_cast<uint4*>(sAc + (s >> 3) * APAD + (s & 7) * 8) = ar[i];
        }
        __syncthreads();

        if (kc + 1 < NCHUNK) {
            int k0 = (kc + 1) * KC;
#pragma unroll
            for (int i = 0; i < 4; i++) {
                int s = tid + i * NTHR;
                wr[i] = *reinterpret_cast<const uint4*>(
                    Wg + (size_t)(s >> 4) * KTOT + k0 + (s & 15) * 8);
            }
            const __half* Ab = (k0 < 2048) ? (Xg + (size_t)k0 * Bd)
                                           : (Hg + (size_t)(k0 - 2048) * Bd);
#pragma unroll
            for (int i = 0; i < 4; i++) {
                int s = tid + i * NTHR;
                ar[i] = *reinterpret_cast<const uint4*>(Ab + (size_t)(s >> 3) * Bd + (s & 7) * 8);
            }
        }

        unsigned aBase = sptr(sWc + (wm * 16 + (lane & 15)) * WPAD + (lane >> 4) * 8);
        unsigned bBase = sptr(sAc + (lane & 15) * APAD + wn * 32 + (lane >> 4) * 8);
#pragma unroll
        for (int kk = 0; kk < KC / 16; kk++) {
            unsigned a0, a1, a2, a3;
            ldsm4(a0, a1, a2, a3, aBase + kk * 32);
#pragma unroll
            for (int nb2 = 0; nb2 < 2; nb2++) {
                unsigned b0, b1, b2, b3;
                ldsm4t(b0, b1, b2, b3,
                       bBase + (unsigned)((kk * 16 * APAD + nb2 * 16) * 2));
                mma16816(acc[nb2 * 2 + 0], a0, a1, a2, a3, b0, b1);
                mma16816(acc[nb2 * 2 + 1], a0, a1, a2, a3, b2, b3);
            }
        }
        __syncthreads();
    }

    {
        int rbase = wm * 16 + (lane >> 2);
        float bs0 = bias[rbase], bs1 = bias[rbase + 8];
#pragma unroll
        for (int nb = 0; nb < 4; nb++) {
            int cb = wn * 32 + nb * 8 + (lane & 3) * 2;
            sG[rbase * GPAD + cb]           = acc[nb][0] + bs0;
            sG[rbase * GPAD + cb + 1]       = acc[nb][1] + bs0;
            sG[(rbase + 8) * GPAD + cb]     = acc[nb][2] + bs1;
            sG[(rbase + 8) * GPAD + cb + 1] = acc[nb][3] + bs1;
        }
    }
    __syncthreads();
}

__device__ __forceinline__ void pointwise(const float* sG, float* cst,
                                          __half* Hout, int ct, int tid) {
#pragma unroll
    for (int e = 0; e < 4; e++) {
        int idx = tid + e * NTHR;        // 16 hidden x 64 batch
        int b = idx & 63, jj = idx >> 6;
        float gi = sG[jj * GPAD + b];
        float gf = sG[(16 + jj) * GPAD + b];
        float gg = sG[(32 + jj) * GPAD + b];
        float go = sG[(48 + jj) * GPAD + b];
        float c = sgm(gf) * cst[e] + sgm(gi) * tanhf(gg);
        cst[e] = c;
        Hout[(ct * 16 + jj) * Bd + b] = __float2half_rn(sgm(go) * tanhf(c));
    }
}

// ------------------------------- main kernel -------------------------------
__global__ void __launch_bounds__(NTHR, 1)
lstm_main(const float* __restrict__ c0) {
    extern __shared__ char smem[];
    __half* sW = reinterpret_cast<__half*>(smem);
    __half* sA = reinterpret_cast<__half*>(smem + SMEM_W_BYTES);
    float*  sG = reinterpret_cast<float*>(smem + SMEM_W_BYTES + SMEM_A_BYTES);

    const int tid = threadIdx.x, lane = tid & 31, wid = tid >> 5;
    const int ct = blockIdx.x;

    float cst0[4], cst1[4];
#pragma unroll
    for (int e = 0; e < 4; e++) {
        int idx = tid + e * NTHR;
        int b = idx & 63, j = ct * 16 + (idx >> 6);
        cst0[e] = c0[(size_t)b * Hd + j];
        cst1[e] = c0[(size_t)(Bd + b) * Hd + j];
    }

    const __half* W0 = &g_W[0][ct][0][0];
    const __half* W1 = &g_W[1][ct][0][0];
    const float* bias0 = &g_bias[0][ct][0];
    const float* bias1 = &g_bias[1][ct][0];
    unsigned target = 0;

    for (int t = 0; t < Td; t++) {
        const int p = t & 1;
        const __half* X0  = (t == 0) ? &g_Xzero[0][0] : &g_H1all[t - 1][0][0];
        const __half* Hp0 = &g_H0[p ^ 1][0][0];
        gemm64<Kd>(W0, X0, Hp0, sW, sA, sG, bias0, tid, lane, wid);
        pointwise(sG, cst0, &g_H0[p][0][0], ct, tid);
        gridbar(target);

        const __half* X1  = &g_H0[p][0][0];
        const __half* Hp1 = (t == 0) ? &g_H1init[0][0] : &g_H1all[t - 1][0][0];
        gemm64<Kd>(W1, X1, Hp1, sW, sA, sG, bias1, tid, lane, wid);
        pointwise(sG, cst1, &g_H1all[t][0][0], ct, tid);
        gridbar(target);
    }
}

// --------------------------- output projection -----------------------------
// y[t] = Wout @ h1[t] + b_out, done once for all t in parallel.
__global__ void __launch_bounds__(NTHR)
proj_kernel(float* __restrict__ out) {
    extern __shared__ char smem[];
    __half* sW = reinterpret_cast<__half*>(smem);
    __half* sA = reinterpret_cast<__half*>(smem + SMEM_W_BYTES);
    float*  sG = reinterpret_cast<float*>(smem + SMEM_W_BYTES + SMEM_A_BYTES);

    const int tid = threadIdx.x, lane = tid & 31, wid = tid >> 5;
    const int bx = blockIdx.x;   // out-row block (16)
    const int t  = blockIdx.y;   // time step (256)

    gemm64<Hd>(&g_WoutH[bx * 64][0], &g_H1all[t][0][0], &g_H1all[t][0][0],
               sW, sA, sG, &g_bout[bx * 64], tid, lane, wid);

#pragma unroll
    for (int e = 0; e < 16; e++) {
        int idx = tid + e * NTHR;
        int b = idx >> 6, oo = idx & 63;
        out[((size_t)(t * Bd + b)) * OUTD + bx * 64 + oo] = sG[oo * GPAD + b];
    }
}

// ------------------------------- entry point -------------------------------
extern "C" void kernel_launch(void* const* d_in, const int* in_sizes, int n_in,
                              void* d_out, int out_size) {
    const float* h0   = (const float*)d_in[0];
    const float* c0   = (const float*)d_in[1];
    const float* Wih  = (const float*)d_in[2];
    const float* Whh  = (const float*)d_in[3];
    const float* bih  = (const float*)d_in[4];
    const float* bhh  = (const float*)d_in[5];
    const float* Wout = (const float*)d_in[6];
    const float* bout = (const float*)d_in[7];
    float* out = (float*)d_out;

    cudaFuncSetAttribute(lstm_main, cudaFuncAttributeMaxDynamicSharedMemorySize, SMEM_BYTES);
    cudaFuncSetAttribute(proj_kernel, cudaFuncAttributeMaxDynamicSharedMemorySize, SMEM_BYTES);

    pack_w_kernel<<<65536, 256>>>(Wih, Whh);
    pack_wout_kernel<<<2048, 256>>>(Wout);
    pack_misc_kernel<<<512, 256>>>(h0, bih, bhh, bout);  // also resets g_count
    lstm_main<<<NCTA, NTHR, SMEM_BYTES>>>(c0);
    proj_kernel<<<dim3(16, Td), NTHR, SMEM_BYTES>>>(out);
}